// round 8
// baseline (speedup 1.0000x reference)
#include <cuda_runtime.h>
#include <cstdint>
#include <cstddef>

#define B_TOT 512
#define S_LEN 256
#define T_TAG 128
#define NB 4
#define NCTA 128
#define NTHREADS 256
#define LOG2E 1.4426950408889634f
#define LN2   0.6931471805599453f

__device__ float g_partial[NCTA];
__device__ int g_count = 0;

__device__ __forceinline__ float warp_max(float v) {
#pragma unroll
    for (int o = 16; o > 0; o >>= 1)
        v = fmaxf(v, __shfl_xor_sync(0xffffffffu, v, o));
    return v;
}
__device__ __forceinline__ float warp_sum(float v) {
#pragma unroll
    for (int o = 16; o > 0; o >>= 1)
        v += __shfl_xor_sync(0xffffffffu, v, o);
    return v;
}
__device__ __forceinline__ unsigned long long dup2(float e) {
    unsigned long long r;
    asm("mov.b64 %0, {%1, %1};" : "=l"(r) : "f"(e));
    return r;
}
__device__ __forceinline__ void fma2(unsigned long long& acc, unsigned long long a,
                                     unsigned long long b) {
    asm("fma.rn.f32x2 %0, %1, %2, %0;" : "+l"(acc) : "l"(a), "l"(b));
}
__device__ __forceinline__ unsigned long long add2(unsigned long long a,
                                                   unsigned long long b) {
    unsigned long long r;
    asm("add.rn.f32x2 %0, %1, %2;" : "=l"(r) : "l"(a), "l"(b));
    return r;
}
__device__ __forceinline__ void unpack2(unsigned long long v, float& lo, float& hi) {
    asm("mov.b64 {%0, %1}, %2;" : "=f"(lo), "=f"(hi) : "l"(v));
}

__global__ __launch_bounds__(NTHREADS, 1) void crf_main(
    const float* __restrict__ emis,
    const void* __restrict__ tags_raw,
    const void* __restrict__ mask_raw,
    const float* __restrict__ trans,
    float* __restrict__ out)
{
    __shared__ __align__(16) float4 p_sh[T_TAG];                   // p, 4 batches per tag
    __shared__ __align__(16) unsigned long long xch[2][8][T_TAG];  // [pair][i-chunk][col]
    __shared__ float2 red_sh[8];
    __shared__ float scr[4];
    __shared__ float gred[8];
    __shared__ unsigned char msk[NB][S_LEN];
    __shared__ int is_last;

    const int tid  = threadIdx.x;
    const int lane = tid & 31;
    const int wid  = tid >> 5;
    // compute role: warp = i-chunk of 16; lane owns 4 adjacent columns
    const int ib   = wid * 16;          // i base
    const int col0 = 4 * lane;          // 4 cols: col0..col0+3
    // reduce role: batch pair p, column c
    const int p    = tid >> 7;
    const int c    = tid & 127;
    const int b0   = blockIdx.x * NB;

    // ---- dtype probes (input-derived, deterministic) ----
    const int* t32 = (const int*)tags_raw;
    const int tags_is_i32 = __syncthreads_or(t32[2 * tid + 1] != 0);
    const int* m32 = (const int*)mask_raw;
    const unsigned char* m8 = (const unsigned char*)mask_raw;
    const bool mask_is_u8 = (m32[0] == 0x01010101);

#define MASK_AT(idx) (mask_is_u8 ? (m8[idx] != 0) : (m32[idx] != 0))
#define TAG_AT(idx)  (tags_is_i32 ? t32[idx] : t32[2 * (idx)])

    // ---- E for my (i-chunk of 16, 4 cols), pre-duplicated f32x2 ----
    unsigned long long E2[16][4];
#pragma unroll
    for (int ii = 0; ii < 16; ii++) {
#pragma unroll
        for (int cc = 0; cc < 4; cc++)
            E2[ii][cc] = dup2(__expf(trans[(ib + ii) * T_TAG + col0 + cc]));
    }

    // ---- mask preload to smem ----
    for (int idx = tid; idx < NB * S_LEN; idx += NTHREADS) {
        int nb = idx >> 8, tt = idx & 255;
        msk[nb][tt] = MASK_AT((size_t)(b0 + nb) * S_LEN + tt) ? 1 : 0;
    }

    const size_t ebL = (size_t)(b0 + 2 * p) * S_LEN * T_TAG;   // my low batch
    const size_t ebH = ebL + (size_t)S_LEN * T_TAG;            // my high batch

    // ---- alpha_0 in log2 domain ----
    float aL = emis[ebL + c] * LOG2E;
    float aH = emis[ebH + c] * LOG2E;
    float mnL, mnH;
    {
        float wl = aL, wh = aH;
#pragma unroll
        for (int o = 16; o > 0; o >>= 1) {
            wl = fmaxf(wl, __shfl_xor_sync(0xffffffffu, wl, o));
            wh = fmaxf(wh, __shfl_xor_sync(0xffffffffu, wh, o));
        }
        if (lane == 0) red_sh[wid] = make_float2(wl, wh);
        __syncthreads();   // also covers msk preload
        float2 r0 = red_sh[p * 4], r1 = red_sh[p * 4 + 1];
        float2 r2 = red_sh[p * 4 + 2], r3 = red_sh[p * 4 + 3];
        mnL = fmaxf(fmaxf(r0.x, r1.x), fmaxf(r2.x, r3.x));
        mnH = fmaxf(fmaxf(r0.y, r1.y), fmaxf(r2.y, r3.y));
        ((float2*)&p_sh[c])[p] = make_float2(exp2f(aL - mnL), exp2f(aH - mnH));
        __syncthreads();   // p + red (red reused as mN at t=1)
    }

    // prefetch t=1 (emissions pre-scaled to log2 domain)
    float emL = emis[ebL + T_TAG + c] * LOG2E;
    float emH = emis[ebH + T_TAG + c] * LOG2E;
    bool  kL  = msk[2 * p][1] != 0;
    bool  kH  = msk[2 * p + 1][1] != 0;

    // ---- forward recursion ----
    for (int t = 1; t < S_LEN; t++) {
        // mN = max(alpha_{t-1}) from red_sh (written before last barrier)
        float2 r0 = red_sh[p * 4], r1 = red_sh[p * 4 + 1];
        float2 r2 = red_sh[p * 4 + 2], r3 = red_sh[p * 4 + 3];
        const float mNL = fmaxf(fmaxf(r0.x, r1.x), fmaxf(r2.x, r3.x));
        const float mNH = fmaxf(fmaxf(r0.y, r1.y), fmaxf(r2.y, r3.y));

        // prefetch t+1
        float emNL = 0.f, emNH = 0.f;
        bool  kNL = false, kNH = false;
        if (t + 1 < S_LEN) {
            const size_t toff = (size_t)(t + 1) * T_TAG + c;
            emNL = emis[ebL + toff] * LOG2E;
            emNH = emis[ebH + toff] * LOG2E;
            kNL = msk[2 * p][t + 1] != 0;
            kNH = msk[2 * p + 1][t + 1] != 0;
        }

        // ---- partial dots: my 16 i, 4 cols, both batch pairs ----
        unsigned long long acc0[4] = {0ull, 0ull, 0ull, 0ull};  // pair 0
        unsigned long long acc1[4] = {0ull, 0ull, 0ull, 0ull};  // pair 1
        const ulonglong2* pp = (const ulonglong2*)p_sh + ib;
#pragma unroll
        for (int ii = 0; ii < 16; ii++) {
            ulonglong2 pv = pp[ii];            // 16B broadcast: 4 batches at tag ib+ii
#pragma unroll
            for (int cc = 0; cc < 4; cc++) {
                fma2(acc0[cc], E2[ii][cc], pv.x);
                fma2(acc1[cc], E2[ii][cc], pv.y);
            }
        }
        // store partials: [pair][chunk][col], 2x STS.128 per pair
        *(ulonglong2*)&xch[0][wid][col0]     = make_ulonglong2(acc0[0], acc0[1]);
        *(ulonglong2*)&xch[0][wid][col0 + 2] = make_ulonglong2(acc0[2], acc0[3]);
        *(ulonglong2*)&xch[1][wid][col0]     = make_ulonglong2(acc1[0], acc1[1]);
        *(ulonglong2*)&xch[1][wid][col0 + 2] = make_ulonglong2(acc1[2], acc1[3]);
        __syncthreads();   // BAR1: partials visible

        // ---- reduce 8 chunk-partials for my (pair, col) ----
        unsigned long long s0 = add2(xch[p][0][c], xch[p][1][c]);
        unsigned long long s1 = add2(xch[p][2][c], xch[p][3][c]);
        unsigned long long s2 = add2(xch[p][4][c], xch[p][5][c]);
        unsigned long long s3 = add2(xch[p][6][c], xch[p][7][c]);
        unsigned long long tot = add2(add2(s0, s1), add2(s2, s3));
        float XL, XH;
        unpack2(tot, XL, XH);

        if (kL) aL = mnL + __log2f(XL) + emL;
        if (kH) aH = mnH + __log2f(XH) + emH;
        mnL = mNL; mnH = mNH;

        ((float2*)&p_sh[c])[p] = make_float2(exp2f(aL - mnL), exp2f(aH - mnH));
        // two independent shfl-max chains, interleaved so they pipeline
        float wl = aL, wh = aH;
#pragma unroll
        for (int o = 16; o > 0; o >>= 1) {
            wl = fmaxf(wl, __shfl_xor_sync(0xffffffffu, wl, o));
            wh = fmaxf(wh, __shfl_xor_sync(0xffffffffu, wh, o));
        }
        if (lane == 0) red_sh[wid] = make_float2(wl, wh);

        emL = emNL; emH = emNH; kL = kNL; kH = kNH;
        __syncthreads();   // BAR2: p + red visible
    }

    // ---- log_Z (convert back: ln Z = (mn2 + log2 sum) * ln2) ----
    float sL = warp_sum(exp2f(aL - mnL));
    float sH = warp_sum(exp2f(aH - mnH));
    if (lane == 0) red_sh[wid] = make_float2(sL, sH);
    __syncthreads();
    if (c == 0) {   // tid 0 and 128
        float2 r0 = red_sh[p * 4], r1 = red_sh[p * 4 + 1];
        float2 r2 = red_sh[p * 4 + 2], r3 = red_sh[p * 4 + 3];
        scr[2 * p]     = (mnL + __log2f(r0.x + r1.x + r2.x + r3.x)) * LN2;
        scr[2 * p + 1] = (mnH + __log2f(r0.y + r1.y + r2.y + r3.y)) * LN2;
    }

    // ---- gold: batch nb = tid>>6, 64 threads each ----
    {
        const int nb = tid >> 6;
        const int t0 = tid & 63;
        const size_t tb  = (size_t)(b0 + nb) * S_LEN;
        const size_t ebn = tb * T_TAG;
        float gg = 0.f;
        for (int tt = t0; tt < S_LEN; tt += 64) {
            int tg = TAG_AT(tb + tt);
            bool mk = msk[nb][tt] != 0;
            if (mk) gg += emis[ebn + (size_t)tt * T_TAG + tg];
            if (tt + 1 < S_LEN) {
                if (mk && msk[nb][tt + 1]) gg += trans[tg * T_TAG + TAG_AT(tb + tt + 1)];
            }
        }
        gg = warp_sum(gg);
        if (lane == 0) gred[wid] = gg;
    }
    __syncthreads();   // scr + gred visible

    if (tid == 0) {
        float part = 0.f;
#pragma unroll
        for (int nb = 0; nb < NB; nb++)
            part += scr[nb] - (gred[2 * nb] + gred[2 * nb + 1]);
        g_partial[blockIdx.x] = part;
        __threadfence();
        int old = atomicAdd(&g_count, 1);
        is_last = (old == NCTA - 1) ? 1 : 0;
    }
    __syncthreads();

    if (is_last) {
        __threadfence();
        float v = (tid < NCTA) ? __ldcg(&g_partial[tid]) : 0.f;
        v = warp_sum(v);
        if (lane == 0) gred[wid] = v;
        __syncthreads();
        if (tid == 0) {
            float tot = 0.f;
#pragma unroll
            for (int w = 0; w < 8; w++) tot += gred[w];
            out[0] = tot * (1.0f / (float)B_TOT);
            g_count = 0;   // reset for next graph replay
        }
    }
#undef MASK_AT
#undef TAG_AT
}

extern "C" void kernel_launch(void* const* d_in, const int* in_sizes, int n_in,
                              void* d_out, int out_size) {
    const float* emis  = (const float*)d_in[0];
    const void*  tags  = d_in[1];
    const void*  mask  = d_in[2];
    const float* trans = (const float*)d_in[3];
    float* out = (float*)d_out;

    crf_main<<<NCTA, NTHREADS>>>(emis, tags, mask, trans, out);
}

// round 9
// speedup vs baseline: 1.1026x; 1.1026x over previous
#include <cuda_runtime.h>
#include <cstdint>
#include <cstddef>

#define B_TOT 512
#define S_LEN 256
#define T_TAG 128
#define NB 4
#define NCTA 128
#define NTHREADS 256
#define LN2 0.6931471805599453f

__device__ float g_partial[NCTA];
__device__ int g_count = 0;

__device__ __forceinline__ float warp_sum(float v) {
#pragma unroll
    for (int o = 16; o > 0; o >>= 1)
        v += __shfl_xor_sync(0xffffffffu, v, o);
    return v;
}
__device__ __forceinline__ unsigned long long pack2(float lo, float hi) {
    unsigned long long r;
    asm("mov.b64 %0, {%1, %2};" : "=l"(r) : "f"(lo), "f"(hi));
    return r;
}
__device__ __forceinline__ void fma2(unsigned long long& acc, unsigned long long a,
                                     unsigned long long b) {
    asm("fma.rn.f32x2 %0, %1, %2, %0;" : "+l"(acc) : "l"(a), "l"(b));
}
__device__ __forceinline__ unsigned long long add2(unsigned long long a,
                                                   unsigned long long b) {
    unsigned long long r;
    asm("add.rn.f32x2 %0, %1, %2;" : "=l"(r) : "l"(a), "l"(b));
    return r;
}
__device__ __forceinline__ void unpack2(unsigned long long v, float& lo, float& hi) {
    asm("mov.b64 {%0, %1}, %2;" : "=f"(lo), "=f"(hi) : "l"(v));
}

__global__ __launch_bounds__(NTHREADS, 1) void crf_main(
    const float* __restrict__ emis,
    const void* __restrict__ tags_raw,
    const void* __restrict__ mask_raw,
    const float* __restrict__ trans,
    float* __restrict__ out)
{
    __shared__ __align__(16) float p_lin[NB][T_TAG];      // v (linear alpha), [batch][tag]
    __shared__ __align__(16) float2 xch[8][2][T_TAG];     // [i-chunk][pair][col]
    __shared__ float2 red_sh[8];                          // per-warp maxes
    __shared__ float scr[4];
    __shared__ float gred[8];
    __shared__ unsigned char msk[NB][S_LEN];
    __shared__ int is_last;

    const int tid  = threadIdx.x;
    const int lane = tid & 31;
    const int wid  = tid >> 5;
    const int ibase = wid * 16;        // compute role: 16 i's (8 i-pairs) per warp
    const int p_   = tid >> 7;         // reduce role: batch pair
    const int c    = tid & 127;        // reduce role: column
    const int b0   = blockIdx.x * NB;

    // ---- dtype probes (input-derived, deterministic) ----
    const int* t32 = (const int*)tags_raw;
    const int tags_is_i32 = __syncthreads_or(t32[2 * tid + 1] != 0);
    const int* m32 = (const int*)mask_raw;
    const unsigned char* m8 = (const unsigned char*)mask_raw;
    const bool mask_is_u8 = (m32[0] == 0x01010101);

#define MASK_AT(idx) (mask_is_u8 ? (m8[idx] != 0) : (m32[idx] != 0))
#define TAG_AT(idx)  (tags_is_i32 ? t32[idx] : t32[2 * (idx)])

    // ---- E packed along i: E2[ip][cc] = (E[2ip,col], E[2ip+1,col]), col = lane+32cc ----
    unsigned long long E2[8][4];
#pragma unroll
    for (int ip = 0; ip < 8; ip++) {
#pragma unroll
        for (int cc = 0; cc < 4; cc++) {
            const int col = lane + 32 * cc;
            float elo = __expf(trans[(ibase + 2 * ip)     * T_TAG + col]);
            float ehi = __expf(trans[(ibase + 2 * ip + 1) * T_TAG + col]);
            E2[ip][cc] = pack2(elo, ehi);
        }
    }

    // ---- mask preload ----
    for (int idx = tid; idx < NB * S_LEN; idx += NTHREADS) {
        int nb = idx >> 8, tt = idx & 255;
        msk[nb][tt] = MASK_AT((size_t)(b0 + nb) * S_LEN + tt) ? 1 : 0;
    }

    const size_t ebL = (size_t)(b0 + 2 * p_) * S_LEN * T_TAG;
    const size_t ebH = ebL + (size_t)S_LEN * T_TAG;

    // ---- v0 = exp(em0), lsum = 0 ----
    float vL = __expf(emis[ebL + c]);
    float vH = __expf(emis[ebH + c]);
    float lsumL = 0.f, lsumH = 0.f;
    p_lin[2 * p_][c]     = vL;
    p_lin[2 * p_ + 1][c] = vH;
    {
        float wl = vL, wh = vH;
#pragma unroll
        for (int o = 16; o > 0; o >>= 1) {
            wl = fmaxf(wl, __shfl_xor_sync(0xffffffffu, wl, o));
            wh = fmaxf(wh, __shfl_xor_sync(0xffffffffu, wh, o));
        }
        if (lane == 0) red_sh[wid] = make_float2(wl, wh);
    }
    __syncthreads();   // covers p_lin, red_sh, msk, probes

    // prefetch t=1
    float exL = __expf(emis[ebL + T_TAG + c]);
    float exH = __expf(emis[ebH + T_TAG + c]);
    bool  kL  = msk[2 * p_][1] != 0;
    bool  kH  = msk[2 * p_ + 1][1] != 0;

    // ---- forward recursion (linear domain, deferred 1/m rescale) ----
    for (int t = 1; t < S_LEN; t++) {
        // m = max(v_{t-1}) per batch, from red_sh
        float2 r0 = red_sh[p_ * 4], r1 = red_sh[p_ * 4 + 1];
        float2 r2 = red_sh[p_ * 4 + 2], r3 = red_sh[p_ * 4 + 3];
        const float mL = fmaxf(fmaxf(r0.x, r1.x), fmaxf(r2.x, r3.x));
        const float mH = fmaxf(fmaxf(r0.y, r1.y), fmaxf(r2.y, r3.y));
        const float sL = __fdividef(1.f, mL), sH = __fdividef(1.f, mH);
        const float lgL = __log2f(mL), lgH = __log2f(mH);
        const float emsL = exL * sL, emsH = exH * sH;

        // prefetch t+1
        float exNL = 0.f, exNH = 0.f;
        bool  kNL = false, kNH = false;
        if (t + 1 < S_LEN) {
            const size_t toff = (size_t)(t + 1) * T_TAG + c;
            exNL = __expf(emis[ebL + toff]);
            exNH = __expf(emis[ebH + toff]);
            kNL = msk[2 * p_][t + 1] != 0;
            kNH = msk[2 * p_ + 1][t + 1] != 0;
        }

        // ---- dot: acc[b][cc] packs (even-i, odd-i) partial sums ----
        unsigned long long acc[4][4];
#pragma unroll
        for (int b = 0; b < 4; b++)
#pragma unroll
            for (int cc = 0; cc < 4; cc++) acc[b][cc] = 0ull;
#pragma unroll
        for (int q = 0; q < 4; q++) {          // q = group of 2 i-pairs (4 i's)
#pragma unroll
            for (int b = 0; b < 4; b++) {
                ulonglong2 pv = *(const ulonglong2*)&p_lin[b][ibase + 4 * q];
#pragma unroll
                for (int cc = 0; cc < 4; cc++) {
                    fma2(acc[b][cc], E2[2 * q][cc],     pv.x);
                    fma2(acc[b][cc], E2[2 * q + 1][cc], pv.y);
                }
            }
        }
        // fold even/odd halves and store partials (conflict-free STS.64)
#pragma unroll
        for (int cc = 0; cc < 4; cc++) {
            float l0, h0, l1, h1, l2, h2, l3, h3;
            unpack2(acc[0][cc], l0, h0);
            unpack2(acc[1][cc], l1, h1);
            unpack2(acc[2][cc], l2, h2);
            unpack2(acc[3][cc], l3, h3);
            xch[wid][0][lane + 32 * cc] = make_float2(l0 + h0, l1 + h1);
            xch[wid][1][lane + 32 * cc] = make_float2(l2 + h2, l3 + h3);
        }
        __syncthreads();   // BAR1

        // ---- reduce 8 chunk partials for my (pair, col) ----
        const unsigned long long* xc = (const unsigned long long*)&xch[0][p_][c];
        // stride between chunks = 2*T_TAG float2 = 256*8 bytes = 256 u64
        unsigned long long u0 = add2(xc[0],        xc[256]);
        unsigned long long u1 = add2(xc[2 * 256],  xc[3 * 256]);
        unsigned long long u2 = add2(xc[4 * 256],  xc[5 * 256]);
        unsigned long long u3 = add2(xc[6 * 256],  xc[7 * 256]);
        unsigned long long ut = add2(add2(u0, u1), add2(u2, u3));
        float XL, XH;
        unpack2(ut, XL, XH);

        if (kL) { vL = XL * emsL; lsumL += lgL; }
        if (kH) { vH = XH * emsH; lsumH += lgH; }
        p_lin[2 * p_][c]     = vL;
        p_lin[2 * p_ + 1][c] = vH;

        float wl = vL, wh = vH;
#pragma unroll
        for (int o = 16; o > 0; o >>= 1) {
            wl = fmaxf(wl, __shfl_xor_sync(0xffffffffu, wl, o));
            wh = fmaxf(wh, __shfl_xor_sync(0xffffffffu, wh, o));
        }
        if (lane == 0) red_sh[wid] = make_float2(wl, wh);

        exL = exNL; exH = exNH; kL = kNL; kH = kNH;
        __syncthreads();   // BAR2
    }

    // ---- log_Z: ln Z = (log2(sum v) + lsum) * ln2 ----
    float suL = warp_sum(vL);
    float suH = warp_sum(vH);
    if (lane == 0) red_sh[wid] = make_float2(suL, suH);
    __syncthreads();
    if (c == 0) {   // tid 0 and 128
        float2 r0 = red_sh[p_ * 4], r1 = red_sh[p_ * 4 + 1];
        float2 r2 = red_sh[p_ * 4 + 2], r3 = red_sh[p_ * 4 + 3];
        scr[2 * p_]     = (__log2f(r0.x + r1.x + r2.x + r3.x) + lsumL) * LN2;
        scr[2 * p_ + 1] = (__log2f(r0.y + r1.y + r2.y + r3.y) + lsumH) * LN2;
    }

    // ---- gold: batch nb = tid>>6, 64 threads each ----
    {
        const int nb = tid >> 6;
        const int t0 = tid & 63;
        const size_t tb  = (size_t)(b0 + nb) * S_LEN;
        const size_t ebn = tb * T_TAG;
        float gg = 0.f;
        for (int tt = t0; tt < S_LEN; tt += 64) {
            int tg = TAG_AT(tb + tt);
            bool mk = msk[nb][tt] != 0;
            if (mk) gg += emis[ebn + (size_t)tt * T_TAG + tg];
            if (tt + 1 < S_LEN) {
                if (mk && msk[nb][tt + 1]) gg += trans[tg * T_TAG + TAG_AT(tb + tt + 1)];
            }
        }
        gg = warp_sum(gg);
        if (lane == 0) gred[wid] = gg;
    }
    __syncthreads();   // scr + gred visible

    if (tid == 0) {
        float part = 0.f;
#pragma unroll
        for (int nb = 0; nb < NB; nb++)
            part += scr[nb] - (gred[2 * nb] + gred[2 * nb + 1]);
        g_partial[blockIdx.x] = part;
        __threadfence();
        int old = atomicAdd(&g_count, 1);
        is_last = (old == NCTA - 1) ? 1 : 0;
    }
    __syncthreads();

    if (is_last) {
        __threadfence();
        float v = (tid < NCTA) ? __ldcg(&g_partial[tid]) : 0.f;
        v = warp_sum(v);
        if (lane == 0) gred[wid] = v;
        __syncthreads();
        if (tid == 0) {
            float tot = 0.f;
#pragma unroll
            for (int w = 0; w < 8; w++) tot += gred[w];
            out[0] = tot * (1.0f / (float)B_TOT);
            g_count = 0;   // reset for next graph replay
        }
    }
#undef MASK_AT
#undef TAG_AT
}

extern "C" void kernel_launch(void* const* d_in, const int* in_sizes, int n_in,
                              void* d_out, int out_size) {
    const float* emis  = (const float*)d_in[0];
    const void*  tags  = d_in[1];
    const void*  mask  = d_in[2];
    const float* trans = (const float*)d_in[3];
    float* out = (float*)d_out;

    crf_main<<<NCTA, NTHREADS>>>(emis, tags, mask, trans, out);
}

// round 10
// speedup vs baseline: 1.2540x; 1.1373x over previous
#include <cuda_runtime.h>
#include <cstdint>
#include <cstddef>

#define B_TOT 512
#define S_LEN 256
#define T_TAG 128
#define NB 2
#define NCTA (B_TOT / NB)      // 256 CTAs, 2 per SM
#define NTHREADS 256
#define LN2 0.6931471805599453f

__device__ float g_partial[NCTA];
__device__ int g_count = 0;

__device__ __forceinline__ float warp_sum(float v) {
#pragma unroll
    for (int o = 16; o > 0; o >>= 1)
        v += __shfl_xor_sync(0xffffffffu, v, o);
    return v;
}
__device__ __forceinline__ float warp_max(float v) {
#pragma unroll
    for (int o = 16; o > 0; o >>= 1)
        v = fmaxf(v, __shfl_xor_sync(0xffffffffu, v, o));
    return v;
}
__device__ __forceinline__ unsigned long long pack2(float lo, float hi) {
    unsigned long long r;
    asm("mov.b64 %0, {%1, %2};" : "=l"(r) : "f"(lo), "f"(hi));
    return r;
}
__device__ __forceinline__ void fma2(unsigned long long& acc, unsigned long long a,
                                     unsigned long long b) {
    asm("fma.rn.f32x2 %0, %1, %2, %0;" : "+l"(acc) : "l"(a), "l"(b));
}
__device__ __forceinline__ void unpack2(unsigned long long v, float& lo, float& hi) {
    asm("mov.b64 {%0, %1}, %2;" : "=f"(lo), "=f"(hi) : "l"(v));
}

__global__ __launch_bounds__(NTHREADS, 2) void crf_main(
    const float* __restrict__ emis,
    const void* __restrict__ tags_raw,
    const void* __restrict__ mask_raw,
    const float* __restrict__ trans,
    float* __restrict__ out)
{
    __shared__ __align__(16) float p_lin[NB][T_TAG];   // v (linear alpha), [batch][tag]
    __shared__ __align__(16) float xch[NB][8][T_TAG];  // per-batch planes: [chunk][col]
    __shared__ float red_sh[8];                        // per-warp maxes
    __shared__ float scr[NB];
    __shared__ float gred[8];
    __shared__ unsigned char msk[NB][S_LEN];
    __shared__ int is_last;

    const int tid  = threadIdx.x;
    const int lane = tid & 31;
    const int wid  = tid >> 5;
    const int ibase = wid * 16;        // compute role: 16 i's (8 i-pairs) per warp
    const int bb   = tid >> 7;         // reduce role: batch (0/1)
    const int c    = tid & 127;        // reduce role: column
    const int b0   = blockIdx.x * NB;

    // ---- dtype probes (input-derived, deterministic) ----
    const int* t32 = (const int*)tags_raw;
    const int tags_is_i32 = __syncthreads_or(t32[2 * tid + 1] != 0);
    const int* m32 = (const int*)mask_raw;
    const unsigned char* m8 = (const unsigned char*)mask_raw;
    const bool mask_is_u8 = (m32[0] == 0x01010101);

#define MASK_AT(idx) (mask_is_u8 ? (m8[idx] != 0) : (m32[idx] != 0))
#define TAG_AT(idx)  (tags_is_i32 ? t32[idx] : t32[2 * (idx)])

    // ---- E packed along i: E2[ip][cc] = (E[2ip,col], E[2ip+1,col]), col = lane+32cc ----
    unsigned long long E2[8][4];
#pragma unroll
    for (int ip = 0; ip < 8; ip++) {
#pragma unroll
        for (int cc = 0; cc < 4; cc++) {
            const int col = lane + 32 * cc;
            float elo = __expf(trans[(ibase + 2 * ip)     * T_TAG + col]);
            float ehi = __expf(trans[(ibase + 2 * ip + 1) * T_TAG + col]);
            E2[ip][cc] = pack2(elo, ehi);
        }
    }

    // ---- mask preload ----
    for (int idx = tid; idx < NB * S_LEN; idx += NTHREADS) {
        int nb = idx >> 8, tt = idx & 255;
        msk[nb][tt] = MASK_AT((size_t)(b0 + nb) * S_LEN + tt) ? 1 : 0;
    }

    const size_t eb = (size_t)(b0 + bb) * S_LEN * T_TAG;   // my batch's emissions

    // ---- v0 = exp(em0), lsum = 0 ----
    float v = __expf(emis[eb + c]);
    float lsum = 0.f;
    p_lin[bb][c] = v;
    {
        float wl = warp_max(v);
        if (lane == 0) red_sh[wid] = wl;
    }
    __syncthreads();   // covers p_lin, red_sh, msk, probes

    // prefetch t=1
    float ex = __expf(emis[eb + T_TAG + c]);
    bool  k  = msk[bb][1] != 0;

    // ---- forward recursion (linear domain, deferred 1/m rescale) ----
    for (int t = 1; t < S_LEN; t++) {
        // m = max(v_{t-1}) for my batch
        const int rbase = bb * 4;
        const float m = fmaxf(fmaxf(red_sh[rbase], red_sh[rbase + 1]),
                              fmaxf(red_sh[rbase + 2], red_sh[rbase + 3]));
        const float s  = __fdividef(1.f, m);
        const float lg = __log2f(m);
        const float ems = ex * s;

        // prefetch t+1
        float exN = 0.f;
        bool  kN = false;
        if (t + 1 < S_LEN) {
            exN = __expf(emis[eb + (size_t)(t + 1) * T_TAG + c]);
            kN = msk[bb][t + 1] != 0;
        }

        // ---- dot: acc[b][cc] packs (even-i, odd-i) partial sums ----
        unsigned long long acc[NB][4];
#pragma unroll
        for (int b = 0; b < NB; b++)
#pragma unroll
            for (int cc = 0; cc < 4; cc++) acc[b][cc] = 0ull;
#pragma unroll
        for (int q = 0; q < 4; q++) {          // q = group of 4 i's
#pragma unroll
            for (int b = 0; b < NB; b++) {
                ulonglong2 pv = *(const ulonglong2*)&p_lin[b][ibase + 4 * q];
#pragma unroll
                for (int cc = 0; cc < 4; cc++) {
                    fma2(acc[b][cc], E2[2 * q][cc],     pv.x);
                    fma2(acc[b][cc], E2[2 * q + 1][cc], pv.y);
                }
            }
        }
        // fold even/odd halves, store to per-batch planes (conflict-free STS.32)
#pragma unroll
        for (int cc = 0; cc < 4; cc++) {
            const int col = lane + 32 * cc;
            float l0, h0, l1, h1;
            unpack2(acc[0][cc], l0, h0);
            unpack2(acc[1][cc], l1, h1);
            xch[0][wid][col] = l0 + h0;
            xch[1][wid][col] = l1 + h1;
        }
        __syncthreads();   // BAR1

        // ---- reduce 8 chunk partials for my (batch, col) ----
        const float* xp = &xch[bb][0][c];
        float X = ((xp[0]         + xp[T_TAG])     + (xp[2 * T_TAG] + xp[3 * T_TAG]))
                + ((xp[4 * T_TAG] + xp[5 * T_TAG]) + (xp[6 * T_TAG] + xp[7 * T_TAG]));

        if (k) { v = X * ems; lsum += lg; }
        p_lin[bb][c] = v;

        float wl = warp_max(v);
        if (lane == 0) red_sh[wid] = wl;

        ex = exN; k = kN;
        __syncthreads();   // BAR2
    }

    // ---- log_Z: ln Z = (log2(sum v) + lsum) * ln2 ----
    float su = warp_sum(v);
    if (lane == 0) red_sh[wid] = su;
    __syncthreads();
    if (c == 0) {   // tid 0 and 128
        const int rbase = bb * 4;
        scr[bb] = (__log2f(red_sh[rbase] + red_sh[rbase + 1] +
                           red_sh[rbase + 2] + red_sh[rbase + 3]) + lsum) * LN2;
    }

    // ---- gold: batch bb, 128 threads each ----
    {
        const size_t tb  = (size_t)(b0 + bb) * S_LEN;
        const size_t ebn = tb * T_TAG;
        float gg = 0.f;
        for (int tt = c; tt < S_LEN; tt += 128) {
            int tg = TAG_AT(tb + tt);
            bool mk = msk[bb][tt] != 0;
            if (mk) gg += emis[ebn + (size_t)tt * T_TAG + tg];
            if (tt + 1 < S_LEN) {
                if (mk && msk[bb][tt + 1]) gg += trans[tg * T_TAG + TAG_AT(tb + tt + 1)];
            }
        }
        gg = warp_sum(gg);
        if (lane == 0) gred[wid] = gg;
    }
    __syncthreads();   // scr + gred visible

    if (tid == 0) {
        float part = (scr[0] - (gred[0] + gred[1] + gred[2] + gred[3]))
                   + (scr[1] - (gred[4] + gred[5] + gred[6] + gred[7]));
        g_partial[blockIdx.x] = part;
        __threadfence();
        int old = atomicAdd(&g_count, 1);
        is_last = (old == NCTA - 1) ? 1 : 0;
    }
    __syncthreads();

    if (is_last) {
        __threadfence();
        float vv = (tid < NCTA) ? __ldcg(&g_partial[tid]) : 0.f;
        vv = warp_sum(vv);
        if (lane == 0) gred[wid] = vv;
        __syncthreads();
        if (tid == 0) {
            float tot = 0.f;
#pragma unroll
            for (int w = 0; w < 8; w++) tot += gred[w];
            out[0] = tot * (1.0f / (float)B_TOT);
            g_count = 0;   // reset for next graph replay
        }
    }
#undef MASK_AT
#undef TAG_AT
}

extern "C" void kernel_launch(void* const* d_in, const int* in_sizes, int n_in,
                              void* d_out, int out_size) {
    const float* emis  = (const float*)d_in[0];
    const void*  tags  = d_in[1];
    const void*  mask  = d_in[2];
    const float* trans = (const float*)d_in[3];
    float* out = (float*)d_out;

    crf_main<<<NCTA, NTHREADS>>>(emis, tags, mask, trans, out);
}

// round 11
// speedup vs baseline: 1.3579x; 1.0829x over previous
#include <cuda_runtime.h>
#include <cstdint>
#include <cstddef>

#define B_TOT 512
#define S_LEN 256
#define T_TAG 128
#define NB 2
#define NCTA (B_TOT / NB)      // 256 CTAs, 2 per SM
#define NTHREADS 256
#define LN2 0.6931471805599453f

__device__ float g_partial[NCTA];
__device__ int g_count = 0;

__device__ __forceinline__ float warp_sum(float v) {
#pragma unroll
    for (int o = 16; o > 0; o >>= 1)
        v += __shfl_xor_sync(0xffffffffu, v, o);
    return v;
}
__device__ __forceinline__ float warp_max(float v) {
#pragma unroll
    for (int o = 16; o > 0; o >>= 1)
        v = fmaxf(v, __shfl_xor_sync(0xffffffffu, v, o));
    return v;
}
__device__ __forceinline__ unsigned long long pack2(float lo, float hi) {
    unsigned long long r;
    asm("mov.b64 %0, {%1, %2};" : "=l"(r) : "f"(lo), "f"(hi));
    return r;
}
__device__ __forceinline__ void fma2(unsigned long long& acc, unsigned long long a,
                                     unsigned long long b) {
    asm("fma.rn.f32x2 %0, %1, %2, %0;" : "+l"(acc) : "l"(a), "l"(b));
}
__device__ __forceinline__ unsigned long long add2(unsigned long long a,
                                                   unsigned long long b) {
    unsigned long long r;
    asm("add.rn.f32x2 %0, %1, %2;" : "=l"(r) : "l"(a), "l"(b));
    return r;
}
__device__ __forceinline__ void unpack2(unsigned long long v, float& lo, float& hi) {
    asm("mov.b64 {%0, %1}, %2;" : "=f"(lo), "=f"(hi) : "l"(v));
}

__global__ __launch_bounds__(NTHREADS, 2) void crf_main(
    const float* __restrict__ emis,
    const void* __restrict__ tags_raw,
    const void* __restrict__ mask_raw,
    const float* __restrict__ trans,
    float* __restrict__ out)
{
    __shared__ __align__(16) float p_lin[NB][T_TAG];     // v (linear alpha), [batch][tag]
    __shared__ __align__(16) float2 xch[NB][4][T_TAG];   // [batch][chunk-pair][col]
    __shared__ float red_sh[8];                          // per-warp maxes
    __shared__ float scr[NB];
    __shared__ float gred[8];
    __shared__ unsigned char msk[NB][S_LEN];
    __shared__ int is_last;

    const int tid  = threadIdx.x;
    const int lane = tid & 31;
    const int wid  = tid >> 5;
    const int ibase = wid * 16;        // compute role: 16 i's (8 i-pairs) per warp
    const int cp   = wid >> 1;         // chunk pair index
    const int par  = wid & 1;          // component within float2
    const int bb   = tid >> 7;         // reduce role: batch (0/1)
    const int c    = tid & 127;        // reduce role: column
    const int b0   = blockIdx.x * NB;

    // ---- dtype probes (input-derived, deterministic) ----
    const int* t32 = (const int*)tags_raw;
    const int tags_is_i32 = __syncthreads_or(t32[2 * tid + 1] != 0);
    const int* m32 = (const int*)mask_raw;
    const unsigned char* m8 = (const unsigned char*)mask_raw;
    const bool mask_is_u8 = (m32[0] == 0x01010101);

#define MASK_AT(idx) (mask_is_u8 ? (m8[idx] != 0) : (m32[idx] != 0))
#define TAG_AT(idx)  (tags_is_i32 ? t32[idx] : t32[2 * (idx)])

    // ---- E packed along i: E2[ip][cc] = (E[2ip,col], E[2ip+1,col]), col = lane+32cc ----
    unsigned long long E2[8][4];
#pragma unroll
    for (int ip = 0; ip < 8; ip++) {
#pragma unroll
        for (int cc = 0; cc < 4; cc++) {
            const int col = lane + 32 * cc;
            float elo = __expf(trans[(ibase + 2 * ip)     * T_TAG + col]);
            float ehi = __expf(trans[(ibase + 2 * ip + 1) * T_TAG + col]);
            E2[ip][cc] = pack2(elo, ehi);
        }
    }

    // ---- mask preload ----
    for (int idx = tid; idx < NB * S_LEN; idx += NTHREADS) {
        int nb = idx >> 8, tt = idx & 255;
        msk[nb][tt] = MASK_AT((size_t)(b0 + nb) * S_LEN + tt) ? 1 : 0;
    }

    const size_t eb = (size_t)(b0 + bb) * S_LEN * T_TAG;   // my batch's emissions

    // ---- v0 = exp(em0), lsum = 0 ----
    float v = __expf(emis[eb + c]);
    float lsum = 0.f;
    p_lin[bb][c] = v;
    __syncthreads();   // covers p_lin, msk, probes

    // prefetch t=1
    float ex = __expf(emis[eb + T_TAG + c]);
    bool  k  = msk[bb][1] != 0;

    // ---- forward recursion (linear domain, rescale every 4th step) ----
    for (int t = 1; t < S_LEN; t++) {
        const bool resc = (t & 3) == 0;
        float s = 1.f, lg = 0.f;
        if (resc) {
            const int rbase = bb * 4;
            const float m = fmaxf(fmaxf(red_sh[rbase], red_sh[rbase + 1]),
                                  fmaxf(red_sh[rbase + 2], red_sh[rbase + 3]));
            s  = __fdividef(1.f, m);
            lg = __log2f(m);
        }
        const float ems = resc ? ex * s : ex;

        // prefetch t+1
        float exN = 0.f;
        bool  kN = false;
        if (t + 1 < S_LEN) {
            exN = __expf(emis[eb + (size_t)(t + 1) * T_TAG + c]);
            kN = msk[bb][t + 1] != 0;
        }

        // ---- dot: acc[b][cc] packs (even-i, odd-i) partial sums ----
        unsigned long long acc[NB][4];
#pragma unroll
        for (int b = 0; b < NB; b++)
#pragma unroll
            for (int cc = 0; cc < 4; cc++) acc[b][cc] = 0ull;
#pragma unroll
        for (int q = 0; q < 4; q++) {          // q = group of 4 i's
#pragma unroll
            for (int b = 0; b < NB; b++) {
                ulonglong2 pv = *(const ulonglong2*)&p_lin[b][ibase + 4 * q];
#pragma unroll
                for (int cc = 0; cc < 4; cc++) {
                    fma2(acc[b][cc], E2[2 * q][cc],     pv.x);
                    fma2(acc[b][cc], E2[2 * q + 1][cc], pv.y);
                }
            }
        }
        // fold even/odd halves, store into paired-chunk planes
#pragma unroll
        for (int cc = 0; cc < 4; cc++) {
            const int col = lane + 32 * cc;
            float l0, h0, l1, h1;
            unpack2(acc[0][cc], l0, h0);
            unpack2(acc[1][cc], l1, h1);
            ((float*)&xch[0][cp][col])[par] = l0 + h0;
            ((float*)&xch[1][cp][col])[par] = l1 + h1;
        }
        __syncthreads();   // BAR1

        // ---- reduce 8 chunk partials (4 LDS.64 + add2 tree) ----
        const unsigned long long* xq = (const unsigned long long*)&xch[bb][0][c];
        // stride between chunk-pairs = T_TAG float2 = 128 u64
        unsigned long long u0 = add2(xq[0],       xq[T_TAG]);
        unsigned long long u1 = add2(xq[2 * T_TAG], xq[3 * T_TAG]);
        float xl, xh;
        unpack2(add2(u0, u1), xl, xh);
        const float X = xl + xh;

        if (k) { v = X * ems; lsum += resc ? lg : 0.f; }
        p_lin[bb][c] = v;

        if ((t & 3) == 3) {    // publish max for the rescale at t+1
            float wl = warp_max(v);
            if (lane == 0) red_sh[wid] = wl;
        }

        ex = exN; k = kN;
        __syncthreads();   // BAR2
    }

    // ---- log_Z: ln Z = (log2(sum v) + lsum) * ln2 ----
    float su = warp_sum(v);
    if (lane == 0) red_sh[wid] = su;
    __syncthreads();
    if (c == 0) {   // tid 0 and 128
        const int rbase = bb * 4;
        scr[bb] = (__log2f(red_sh[rbase] + red_sh[rbase + 1] +
                           red_sh[rbase + 2] + red_sh[rbase + 3]) + lsum) * LN2;
    }

    // ---- gold: batch bb, 128 threads each ----
    {
        const size_t tb  = (size_t)(b0 + bb) * S_LEN;
        const size_t ebn = tb * T_TAG;
        float gg = 0.f;
        for (int tt = c; tt < S_LEN; tt += 128) {
            int tg = TAG_AT(tb + tt);
            bool mk = msk[bb][tt] != 0;
            if (mk) gg += emis[ebn + (size_t)tt * T_TAG + tg];
            if (tt + 1 < S_LEN) {
                if (mk && msk[bb][tt + 1]) gg += trans[tg * T_TAG + TAG_AT(tb + tt + 1)];
            }
        }
        gg = warp_sum(gg);
        if (lane == 0) gred[wid] = gg;
    }
    __syncthreads();   // scr + gred visible

    if (tid == 0) {
        float part = (scr[0] - (gred[0] + gred[1] + gred[2] + gred[3]))
                   + (scr[1] - (gred[4] + gred[5] + gred[6] + gred[7]));
        g_partial[blockIdx.x] = part;
        __threadfence();
        int old = atomicAdd(&g_count, 1);
        is_last = (old == NCTA - 1) ? 1 : 0;
    }
    __syncthreads();

    if (is_last) {
        __threadfence();
        float vv = (tid < NCTA) ? __ldcg(&g_partial[tid]) : 0.f;
        vv = warp_sum(vv);
        if (lane == 0) gred[wid] = vv;
        __syncthreads();
        if (tid == 0) {
            float tot = 0.f;
#pragma unroll
            for (int w = 0; w < 8; w++) tot += gred[w];
            out[0] = tot * (1.0f / (float)B_TOT);
            g_count = 0;   // reset for next graph replay
        }
    }
#undef MASK_AT
#undef TAG_AT
}

extern "C" void kernel_launch(void* const* d_in, const int* in_sizes, int n_in,
                              void* d_out, int out_size) {
    const float* emis  = (const float*)d_in[0];
    const void*  tags  = d_in[1];
    const void*  mask  = d_in[2];
    const float* trans = (const float*)d_in[3];
    float* out = (float*)d_out;

    crf_main<<<NCTA, NTHREADS>>>(emis, tags, mask, trans, out);
}